// round 1
// baseline (speedup 1.0000x reference)
#include <cuda_runtime.h>

#define BB 8
#define SS 2048
#define HH 1024
#define NT (BB * SS)   // 16384 tokens

// Scratch (device globals — no allocation allowed in kernel_launch)
__device__ float g_ss[NT];   // score_s per token
__device__ float g_se[NT];   // score_e per token (+ bm folded in)
__device__ int   g_fl[NT];   // bit0 = start_cand, bit1 = end_cand

// ---------------------------------------------------------------------------
// Kernel 1: one warp per token. Computes the 4 length-1024 dot products
// (start_logits[0/1], end_logits[0/1]), candidate flags, and the scalar
// scores score_s / score_e. HBM-read bound (64 MB of rep).
// ---------------------------------------------------------------------------
__global__ void __launch_bounds__(256)
logits_kernel(const float* __restrict__ rep,
              const int*   __restrict__ mask,
              const float* __restrict__ Ws,
              const float* __restrict__ bs,
              const float* __restrict__ We,
              const float* __restrict__ be,
              const float* __restrict__ Wm,
              const float* __restrict__ bm)
{
    int warp = (blockIdx.x * blockDim.x + threadIdx.x) >> 5;
    int lane = threadIdx.x & 31;
    if (warp >= NT) return;

    const float4* r4  = reinterpret_cast<const float4*>(rep + (size_t)warp * HH);
    const float4* w4s = reinterpret_cast<const float4*>(Ws);
    const float4* w4e = reinterpret_cast<const float4*>(We);

    float s0 = 0.f, s1 = 0.f, e0 = 0.f, e1 = 0.f;
    #pragma unroll
    for (int k = 0; k < HH / 128; k++) {
        int idx = k * 32 + lane;               // float4 index: h = 4*idx .. 4*idx+3
        float4 r = r4[idx];
        // Ws is [H,2] row-major: elems 8*idx..8*idx+7 -> two float4
        float4 a = w4s[idx * 2];               // (Ws[h,0],Ws[h,1],Ws[h+1,0],Ws[h+1,1])
        float4 b = w4s[idx * 2 + 1];
        s0 += r.x * a.x + r.y * a.z + r.z * b.x + r.w * b.z;
        s1 += r.x * a.y + r.y * a.w + r.z * b.y + r.w * b.w;
        float4 c = w4e[idx * 2];
        float4 d = w4e[idx * 2 + 1];
        e0 += r.x * c.x + r.y * c.z + r.z * d.x + r.w * d.z;
        e1 += r.x * c.y + r.y * c.w + r.z * d.y + r.w * d.w;
    }
    #pragma unroll
    for (int off = 16; off; off >>= 1) {
        s0 += __shfl_xor_sync(0xffffffffu, s0, off);
        s1 += __shfl_xor_sync(0xffffffffu, s1, off);
        e0 += __shfl_xor_sync(0xffffffffu, e0, off);
        e1 += __shfl_xor_sync(0xffffffffu, e1, off);
    }
    if (lane == 0) {
        s0 += bs[0]; s1 += bs[1];
        e0 += be[0]; e1 += be[1];
        int m  = (mask[warp] != 0);
        int sc = m && (s0 <= s1);
        int ec = m && (e0 <= e1);
        g_ss[warp] = s0 * Wm[0] + s1 * Wm[1];
        g_se[warp] = e0 * Wm[2] + e1 * Wm[3] + bm[0];  // fold bm into score_e
        g_fl[warp] = sc | (ec << 1);
    }
}

// ---------------------------------------------------------------------------
// Kernel 2: one block per (b, i) row; 512 threads x float4 covers S=2048 cols.
// Writes valid (0/1 fp32) and masked_scores. Pure HBM-write bound (256 MB).
// Streaming stores (__stcs): output >> L2, don't pollute it.
// ---------------------------------------------------------------------------
__global__ void __launch_bounds__(512)
pair_kernel(float* __restrict__ out_valid,
            float* __restrict__ out_masked)
{
    const int i = blockIdx.x;
    const int b = blockIdx.y;
    const int t = b * SS + i;

    const float ss = g_ss[t];
    const bool  sc = (g_fl[t] & 1);

    const size_t rowoff = ((size_t)b * SS + i) * SS;
    float4* ov = reinterpret_cast<float4*>(out_valid  + rowoff);
    float4* om = reinterpret_cast<float4*>(out_masked + rowoff);

    const int j4 = threadIdx.x;        // one float4 (4 j's) per thread
    const int j0 = j4 * 4;

    float4 v, m;
    if (!sc || (j0 + 3) < i) {
        v = make_float4(0.f, 0.f, 0.f, 0.f);
        m = v;
    } else {
        const float4 se4 = reinterpret_cast<const float4*>(g_se + b * SS)[j4];
        const int4   fl4 = reinterpret_cast<const int4*>(g_fl + b * SS)[j4];

        float ps; bool val;
        ps = ss + se4.x; val = (fl4.x & 2) && (i <= j0 + 0) && (ps > 0.f);
        v.x = val ? 1.f : 0.f; m.x = val ? ps : 0.f;
        ps = ss + se4.y; val = (fl4.y & 2) && (i <= j0 + 1) && (ps > 0.f);
        v.y = val ? 1.f : 0.f; m.y = val ? ps : 0.f;
        ps = ss + se4.z; val = (fl4.z & 2) && (i <= j0 + 2) && (ps > 0.f);
        v.z = val ? 1.f : 0.f; m.z = val ? ps : 0.f;
        ps = ss + se4.w; val = (fl4.w & 2) && (i <= j0 + 3) && (ps > 0.f);
        v.w = val ? 1.f : 0.f; m.w = val ? ps : 0.f;
    }
    __stcs(ov + j4, v);
    __stcs(om + j4, m);
}

extern "C" void kernel_launch(void* const* d_in, const int* in_sizes, int n_in,
                              void* d_out, int out_size)
{
    const float* rep  = (const float*)d_in[0];
    const int*   mask = (const int*)  d_in[1];
    const float* Ws   = (const float*)d_in[2];
    const float* bs   = (const float*)d_in[3];
    const float* We   = (const float*)d_in[4];
    const float* be   = (const float*)d_in[5];
    const float* Wm   = (const float*)d_in[6];
    const float* bm   = (const float*)d_in[7];

    float* out = (float*)d_out;
    const size_t half = (size_t)BB * SS * SS;   // valid first, masked second

    logits_kernel<<<NT / 8, 256>>>(rep, mask, Ws, bs, We, be, Wm, bm);

    dim3 g2(SS, BB);
    pair_kernel<<<g2, 512>>>(out, out + half);
}